// round 12
// baseline (speedup 1.0000x reference)
#include <cuda_runtime.h>
#include <math.h>

// SimDiff shared-target chains + L2 prefetch, distance 2.
//   right[f,i] = cos(x[f,i], x[f+1,i+1]),  valid i <= 550
//   down [f,i] = cos(x[f,i], x[f+1,i+24]), valid i <= 527
// down(f,i) and right(f,i+23) share target row x[f+1,i+24]; warp walks
// i, i+23, ... with a ping-pong register target row. While segment m
// computes, prefetch.global.L2 pulls segment m+2's rows (~2 segments of
// lead ≈ full DRAM latency) so demand LDG.128s hit L2.

#define FRAMES 64
#define WIDTH  24
#define TPF    552
#define HID    1152
#define TOTAL  (FRAMES * TPF)     // 35328
#define EPS    1e-8f

#define SEG    8                  // positions per warp segment
#define CHPF   23                 // chains per frame
#define SPC    3                  // segments per chain
#define WPF    (CHPF * SPC)       // 69 warps per frame
#define NWARPS ((FRAMES - 1) * WPF)  // 4347 compute warps
#define ROWQ   (HID / 4)          // 288 float4 per row
#define ROWF   HID                // floats per row
#define LINES  (HID * 4 / 128)    // 36 x 128B lines per row

__device__ __forceinline__ void l2_prefetch_row(const float* row, int lane) {
    // 36 lines of 128B: lanes 0..31 cover lines 0..31, lanes 0..3 cover 32..35.
    asm volatile("prefetch.global.L2 [%0];" :: "l"(row + lane * 32));
    if (lane < LINES - 32)
        asm volatile("prefetch.global.L2 [%0];" :: "l"(row + (32 + lane) * 32));
}

__global__ void __launch_bounds__(256, 2)
chain_kernel(const float* __restrict__ x, float* __restrict__ out) {
    const int w    = (blockIdx.x * blockDim.x + threadIdx.x) >> 5;
    const int lane = threadIdx.x & 31;
    if (w >= NWARPS) return;

    const int f  = w / WPF;
    const int r  = w - f * WPF;
    const int c  = r / SPC;           // chain id 0..22
    const int s  = r - c * SPC;       // segment 0..2
    const int col0 = c + CHPF * (SEG * s);   // first position col (<= 390)

    const float4* __restrict__ base = (const float4*)x;

    // Ping-pong target rows + their reduced norms.
    float4 t[2][9];
    float  ntt[2];

    // Preload t_0 = row (f+1, col0+1); prefetch segments 0 and 1.
    {
        // Prefetch segment 0 and 1 rows first (max lead).
        l2_prefetch_row(x + (size_t)(f * TPF + col0) * ROWF, lane);
        l2_prefetch_row(x + (size_t)((f + 1) * TPF + col0 + WIDTH) * ROWF, lane);
        {
            const int c1a = min(col0 + CHPF, TPF - 1);
            const int c1t = min(c1a + WIDTH, TPF - 1);
            l2_prefetch_row(x + (size_t)(f * TPF + c1a) * ROWF, lane);
            l2_prefetch_row(x + (size_t)((f + 1) * TPF + c1t) * ROWF, lane);
        }

        const float4* tp = base + (size_t)((f + 1) * TPF + col0 + 1) * ROWQ + lane;
        #pragma unroll
        for (int u = 0; u < 9; ++u) t[0][u] = tp[u * 32];
        float nt = 0.f;
        #pragma unroll
        for (int u = 0; u < 9; ++u) {
            nt = fmaf(t[0][u].x, t[0][u].x, nt); nt = fmaf(t[0][u].y, t[0][u].y, nt);
            nt = fmaf(t[0][u].z, t[0][u].z, nt); nt = fmaf(t[0][u].w, t[0][u].w, nt);
        }
        #pragma unroll
        for (int off = 16; off; off >>= 1) nt += __shfl_xor_sync(~0u, nt, off);
        ntt[0] = nt;
    }

    #pragma unroll
    for (int m = 0; m < SEG; ++m) {
        const int colm = col0 + CHPF * m;
        const int cur = m & 1, nxt = cur ^ 1;
        const bool vr = (colm <= TPF - 2);          // right valid
        const bool vd = (colm <= TPF - WIDTH - 1);  // down valid
        const int coln = min(colm + WIDTH, TPF - 1); // clamped (masked if !vd)

        const float4* ap = base + (size_t)(f * TPF + colm) * ROWQ + lane;
        const float4* tp = base + (size_t)((f + 1) * TPF + coln) * ROWQ + lane;

        // Prefetch segment m+2's rows (2-segment lead; clamped, in-bounds).
        if (m < SEG - 2) {
            const int cola2 = min(colm + 2 * CHPF, TPF - 1);
            const int colt2 = min(cola2 + WIDTH, TPF - 1);
            l2_prefetch_row(x + (size_t)(f * TPF + cola2) * ROWF, lane);
            l2_prefetch_row(x + (size_t)((f + 1) * TPF + colt2) * ROWF, lane);
        }

        // Load next target row (9 independent LDG.128 in flight).
        #pragma unroll
        for (int u = 0; u < 9; ++u) t[nxt][u] = tp[u * 32];

        float dr = 0.f, dd = 0.f, na = 0.f, nt = 0.f;

        // a-row in bursts of 3, consumed against t[cur] (right) and t[nxt] (down).
        #pragma unroll
        for (int ch = 0; ch < 3; ++ch) {
            float4 av[3];
            #pragma unroll
            for (int u = 0; u < 3; ++u) av[u] = ap[(ch * 3 + u) * 32];
            #pragma unroll
            for (int u = 0; u < 3; ++u) {
                const int k = ch * 3 + u;
                const float4 tc = t[cur][k];
                const float4 tn = t[nxt][k];
                dr = fmaf(av[u].x, tc.x, dr); dr = fmaf(av[u].y, tc.y, dr);
                dr = fmaf(av[u].z, tc.z, dr); dr = fmaf(av[u].w, tc.w, dr);
                dd = fmaf(av[u].x, tn.x, dd); dd = fmaf(av[u].y, tn.y, dd);
                dd = fmaf(av[u].z, tn.z, dd); dd = fmaf(av[u].w, tn.w, dd);
                na = fmaf(av[u].x, av[u].x, na); na = fmaf(av[u].y, av[u].y, na);
                na = fmaf(av[u].z, av[u].z, na); na = fmaf(av[u].w, av[u].w, na);
            }
        }
        #pragma unroll
        for (int u = 0; u < 9; ++u) {
            nt = fmaf(t[nxt][u].x, t[nxt][u].x, nt); nt = fmaf(t[nxt][u].y, t[nxt][u].y, nt);
            nt = fmaf(t[nxt][u].z, t[nxt][u].z, nt); nt = fmaf(t[nxt][u].w, t[nxt][u].w, nt);
        }

        #pragma unroll
        for (int off = 16; off; off >>= 1) {
            dr += __shfl_xor_sync(~0u, dr, off);
            dd += __shfl_xor_sync(~0u, dd, off);
            na += __shfl_xor_sync(~0u, na, off);
            nt += __shfl_xor_sync(~0u, nt, off);
        }
        ntt[nxt] = nt;

        if (lane == 0) {
            const float nA = fmaxf(sqrtf(na), EPS);
            float rr = -1.f, dn = -1.f;
            if (vr) rr = dr / (nA * fmaxf(sqrtf(ntt[cur]), EPS));
            if (vd) dn = dd / (nA * fmaxf(sqrtf(ntt[nxt]), EPS));
            out[f * TPF + colm]         = rr;
            out[TOTAL + f * TPF + colm] = dn;
        }
    }
}

// Frame 63 outputs are all -1 — chains only cover f <= 62.
__global__ void fill_last_frame(float* __restrict__ out) {
    const int idx = blockIdx.x * blockDim.x + threadIdx.x;
    if (idx < TPF) {
        out[(FRAMES - 1) * TPF + idx]         = -1.0f;
        out[TOTAL + (FRAMES - 1) * TPF + idx] = -1.0f;
    }
}

extern "C" void kernel_launch(void* const* d_in, const int* in_sizes, int n_in,
                              void* d_out, int out_size) {
    const float* x = (const float*)d_in[0];
    float* out = (float*)d_out;

    fill_last_frame<<<(TPF + 255) / 256, 256>>>(out);

    const int warps_per_block = 256 / 32;
    const int grid = (NWARPS + warps_per_block - 1) / warps_per_block; // 544
    chain_kernel<<<grid, 256>>>(x, out);
}

// round 13
// speedup vs baseline: 1.1316x; 1.1316x over previous
#include <cuda_runtime.h>
#include <math.h>

// SimDiff shared-target chains + L2 prefetch distance 1 (R10 ordering),
// with the frame-63 "-1" fill folded into spare warps (single launch).
//   right[f,i] = cos(x[f,i], x[f+1,i+1]),  valid i <= 550
//   down [f,i] = cos(x[f,i], x[f+1,i+24]), valid i <= 527
// down(f,i) and right(f,i+23) share target row x[f+1,i+24]; warp walks
// i, i+23, ... with a ping-pong register target row. While segment m
// computes, prefetch.global.L2 pulls segment m+1's rows (issued AFTER the
// demand t-loads — ordering matters: R12 showed prefetch-first regresses).

#define FRAMES 64
#define WIDTH  24
#define TPF    552
#define HID    1152
#define TOTAL  (FRAMES * TPF)     // 35328
#define EPS    1e-8f

#define SEG    8                  // positions per warp segment
#define CHPF   23                 // chains per frame
#define SPC    3                  // segments per chain
#define WPF    (CHPF * SPC)       // 69 warps per frame
#define NWARPS ((FRAMES - 1) * WPF)  // 4347 compute warps
#define ROWQ   (HID / 4)          // 288 float4 per row
#define ROWF   HID                // floats per row
#define LINES  (HID * 4 / 128)    // 36 x 128B lines per row

#define GRID_BLOCKS 546           // 4368 warps: 4347 compute + 21 fill

__device__ __forceinline__ void l2_prefetch_row(const float* row, int lane) {
    // 36 lines of 128B: lanes 0..31 cover lines 0..31, lanes 0..3 cover 32..35.
    asm volatile("prefetch.global.L2 [%0];" :: "l"(row + lane * 32));
    if (lane < LINES - 32)
        asm volatile("prefetch.global.L2 [%0];" :: "l"(row + (32 + lane) * 32));
}

__global__ void __launch_bounds__(256, 2)
chain_kernel(const float* __restrict__ x, float* __restrict__ out) {
    const int w    = (blockIdx.x * blockDim.x + threadIdx.x) >> 5;
    const int lane = threadIdx.x & 31;

    if (w >= NWARPS) {
        // Spare warps: frame 63 outputs are all -1 (chains cover f <= 62).
        const int idx = (w - NWARPS) * 32 + lane;
        if (idx < TPF) {
            out[(FRAMES - 1) * TPF + idx]         = -1.0f;
            out[TOTAL + (FRAMES - 1) * TPF + idx] = -1.0f;
        }
        return;
    }

    const int f  = w / WPF;
    const int r  = w - f * WPF;
    const int c  = r / SPC;           // chain id 0..22
    const int s  = r - c * SPC;       // segment 0..2
    const int col0 = c + CHPF * (SEG * s);   // first position col (<= 390)

    const float4* __restrict__ base = (const float4*)x;

    // Ping-pong target rows + their reduced norms.
    float4 t[2][9];
    float  ntt[2];

    // Preload t_0 = row (f+1, col0+1)  (col0+1 <= 391, in range).
    {
        const float4* tp = base + (size_t)((f + 1) * TPF + col0 + 1) * ROWQ + lane;
        #pragma unroll
        for (int u = 0; u < 9; ++u) t[0][u] = tp[u * 32];
        // Prefetch segment 0's rows while norming t_0.
        l2_prefetch_row(x + (size_t)(f * TPF + col0) * ROWF, lane);
        l2_prefetch_row(x + (size_t)((f + 1) * TPF + col0 + WIDTH) * ROWF, lane);
        float nt = 0.f;
        #pragma unroll
        for (int u = 0; u < 9; ++u) {
            nt = fmaf(t[0][u].x, t[0][u].x, nt); nt = fmaf(t[0][u].y, t[0][u].y, nt);
            nt = fmaf(t[0][u].z, t[0][u].z, nt); nt = fmaf(t[0][u].w, t[0][u].w, nt);
        }
        #pragma unroll
        for (int off = 16; off; off >>= 1) nt += __shfl_xor_sync(~0u, nt, off);
        ntt[0] = nt;
    }

    #pragma unroll
    for (int m = 0; m < SEG; ++m) {
        const int colm = col0 + CHPF * m;
        const int cur = m & 1, nxt = cur ^ 1;
        const bool vr = (colm <= TPF - 2);          // right valid
        const bool vd = (colm <= TPF - WIDTH - 1);  // down valid
        const int coln = min(colm + WIDTH, TPF - 1); // clamped (masked if !vd)

        const float4* ap = base + (size_t)(f * TPF + colm) * ROWQ + lane;
        const float4* tp = base + (size_t)((f + 1) * TPF + coln) * ROWQ + lane;

        // Load next target row (9 independent LDG.128 in flight).
        #pragma unroll
        for (int u = 0; u < 9; ++u) t[nxt][u] = tp[u * 32];

        // Prefetch segment m+1's rows into L2 (after demand loads; no regs).
        if (m < SEG - 1) {
            const int cola2 = colm + CHPF;
            const int colt2 = min(cola2 + WIDTH, TPF - 1);
            l2_prefetch_row(x + (size_t)(f * TPF + cola2) * ROWF, lane);
            l2_prefetch_row(x + (size_t)((f + 1) * TPF + colt2) * ROWF, lane);
        }

        float dr = 0.f, dd = 0.f, na = 0.f, nt = 0.f;

        // a-row in bursts of 3, consumed against t[cur] (right) and t[nxt] (down).
        #pragma unroll
        for (int ch = 0; ch < 3; ++ch) {
            float4 av[3];
            #pragma unroll
            for (int u = 0; u < 3; ++u) av[u] = ap[(ch * 3 + u) * 32];
            #pragma unroll
            for (int u = 0; u < 3; ++u) {
                const int k = ch * 3 + u;
                const float4 tc = t[cur][k];
                const float4 tn = t[nxt][k];
                dr = fmaf(av[u].x, tc.x, dr); dr = fmaf(av[u].y, tc.y, dr);
                dr = fmaf(av[u].z, tc.z, dr); dr = fmaf(av[u].w, tc.w, dr);
                dd = fmaf(av[u].x, tn.x, dd); dd = fmaf(av[u].y, tn.y, dd);
                dd = fmaf(av[u].z, tn.z, dd); dd = fmaf(av[u].w, tn.w, dd);
                na = fmaf(av[u].x, av[u].x, na); na = fmaf(av[u].y, av[u].y, na);
                na = fmaf(av[u].z, av[u].z, na); na = fmaf(av[u].w, av[u].w, na);
            }
        }
        #pragma unroll
        for (int u = 0; u < 9; ++u) {
            nt = fmaf(t[nxt][u].x, t[nxt][u].x, nt); nt = fmaf(t[nxt][u].y, t[nxt][u].y, nt);
            nt = fmaf(t[nxt][u].z, t[nxt][u].z, nt); nt = fmaf(t[nxt][u].w, t[nxt][u].w, nt);
        }

        #pragma unroll
        for (int off = 16; off; off >>= 1) {
            dr += __shfl_xor_sync(~0u, dr, off);
            dd += __shfl_xor_sync(~0u, dd, off);
            na += __shfl_xor_sync(~0u, na, off);
            nt += __shfl_xor_sync(~0u, nt, off);
        }
        ntt[nxt] = nt;

        if (lane == 0) {
            const float nA = fmaxf(sqrtf(na), EPS);
            float rr = -1.f, dn = -1.f;
            if (vr) rr = dr / (nA * fmaxf(sqrtf(ntt[cur]), EPS));
            if (vd) dn = dd / (nA * fmaxf(sqrtf(ntt[nxt]), EPS));
            out[f * TPF + colm]         = rr;
            out[TOTAL + f * TPF + colm] = dn;
        }
    }
}

extern "C" void kernel_launch(void* const* d_in, const int* in_sizes, int n_in,
                              void* d_out, int out_size) {
    const float* x = (const float*)d_in[0];
    float* out = (float*)d_out;

    chain_kernel<<<GRID_BLOCKS, 256>>>(x, out);
}

// round 14
// speedup vs baseline: 1.1626x; 1.0274x over previous
#include <cuda_runtime.h>
#include <math.h>

// SimDiff shared-target chains + L2 prefetch distance 1, t-row only.
//   right[f,i] = cos(x[f,i], x[f+1,i+1]),  valid i <= 550
//   down [f,i] = cos(x[f,i], x[f+1,i+24]), valid i <= 527
// down(f,i) and right(f,i+23) share target row x[f+1,i+24]; warp walks
// i, i+23, ... with a ping-pong register target row. While segment m
// computes, prefetch.global.L2 pulls ONLY segment m+1's t-row (the a-row
// is typically already L2-resident from frame f-1's concurrent t-reads;
// prefetching it double-transits LTS for nothing). Frame-63 fill folded
// into spare warps (single launch).

#define FRAMES 64
#define WIDTH  24
#define TPF    552
#define HID    1152
#define TOTAL  (FRAMES * TPF)     // 35328
#define EPS    1e-8f

#define SEG    8                  // positions per warp segment
#define CHPF   23                 // chains per frame
#define SPC    3                  // segments per chain
#define WPF    (CHPF * SPC)       // 69 warps per frame
#define NWARPS ((FRAMES - 1) * WPF)  // 4347 compute warps
#define ROWQ   (HID / 4)          // 288 float4 per row
#define ROWF   HID                // floats per row
#define LINES  (HID * 4 / 128)    // 36 x 128B lines per row

#define GRID_BLOCKS 546           // 4368 warps: 4347 compute + 21 fill

__device__ __forceinline__ void l2_prefetch_row(const float* row, int lane) {
    // 36 lines of 128B: lanes 0..31 cover lines 0..31, lanes 0..3 cover 32..35.
    asm volatile("prefetch.global.L2 [%0];" :: "l"(row + lane * 32));
    if (lane < LINES - 32)
        asm volatile("prefetch.global.L2 [%0];" :: "l"(row + (32 + lane) * 32));
}

__global__ void __launch_bounds__(256, 2)
chain_kernel(const float* __restrict__ x, float* __restrict__ out) {
    const int w    = (blockIdx.x * blockDim.x + threadIdx.x) >> 5;
    const int lane = threadIdx.x & 31;

    if (w >= NWARPS) {
        // Spare warps: frame 63 outputs are all -1 (chains cover f <= 62).
        const int idx = (w - NWARPS) * 32 + lane;
        if (idx < TPF) {
            out[(FRAMES - 1) * TPF + idx]         = -1.0f;
            out[TOTAL + (FRAMES - 1) * TPF + idx] = -1.0f;
        }
        return;
    }

    const int f  = w / WPF;
    const int r  = w - f * WPF;
    const int c  = r / SPC;           // chain id 0..22
    const int s  = r - c * SPC;       // segment 0..2
    const int col0 = c + CHPF * (SEG * s);   // first position col (<= 390)

    const float4* __restrict__ base = (const float4*)x;

    // Ping-pong target rows + their reduced norms.
    float4 t[2][9];
    float  ntt[2];

    // Preload t_0 = row (f+1, col0+1)  (col0+1 <= 391, in range).
    {
        const float4* tp = base + (size_t)((f + 1) * TPF + col0 + 1) * ROWQ + lane;
        #pragma unroll
        for (int u = 0; u < 9; ++u) t[0][u] = tp[u * 32];
        // Prefetch segment 0's t-row while norming t_0.
        l2_prefetch_row(x + (size_t)((f + 1) * TPF + col0 + WIDTH) * ROWF, lane);
        float nt = 0.f;
        #pragma unroll
        for (int u = 0; u < 9; ++u) {
            nt = fmaf(t[0][u].x, t[0][u].x, nt); nt = fmaf(t[0][u].y, t[0][u].y, nt);
            nt = fmaf(t[0][u].z, t[0][u].z, nt); nt = fmaf(t[0][u].w, t[0][u].w, nt);
        }
        #pragma unroll
        for (int off = 16; off; off >>= 1) nt += __shfl_xor_sync(~0u, nt, off);
        ntt[0] = nt;
    }

    #pragma unroll
    for (int m = 0; m < SEG; ++m) {
        const int colm = col0 + CHPF * m;
        const int cur = m & 1, nxt = cur ^ 1;
        const bool vr = (colm <= TPF - 2);          // right valid
        const bool vd = (colm <= TPF - WIDTH - 1);  // down valid
        const int coln = min(colm + WIDTH, TPF - 1); // clamped (masked if !vd)

        const float4* ap = base + (size_t)(f * TPF + colm) * ROWQ + lane;
        const float4* tp = base + (size_t)((f + 1) * TPF + coln) * ROWQ + lane;

        // Load next target row (9 independent LDG.128 in flight).
        #pragma unroll
        for (int u = 0; u < 9; ++u) t[nxt][u] = tp[u * 32];

        // Prefetch segment m+1's t-row into L2 (after demand loads; no regs).
        if (m < SEG - 1) {
            const int colt2 = min(colm + CHPF + WIDTH, TPF - 1);
            l2_prefetch_row(x + (size_t)((f + 1) * TPF + colt2) * ROWF, lane);
        }

        float dr = 0.f, dd = 0.f, na = 0.f, nt = 0.f;

        // a-row in bursts of 3, consumed against t[cur] (right) and t[nxt] (down).
        #pragma unroll
        for (int ch = 0; ch < 3; ++ch) {
            float4 av[3];
            #pragma unroll
            for (int u = 0; u < 3; ++u) av[u] = ap[(ch * 3 + u) * 32];
            #pragma unroll
            for (int u = 0; u < 3; ++u) {
                const int k = ch * 3 + u;
                const float4 tc = t[cur][k];
                const float4 tn = t[nxt][k];
                dr = fmaf(av[u].x, tc.x, dr); dr = fmaf(av[u].y, tc.y, dr);
                dr = fmaf(av[u].z, tc.z, dr); dr = fmaf(av[u].w, tc.w, dr);
                dd = fmaf(av[u].x, tn.x, dd); dd = fmaf(av[u].y, tn.y, dd);
                dd = fmaf(av[u].z, tn.z, dd); dd = fmaf(av[u].w, tn.w, dd);
                na = fmaf(av[u].x, av[u].x, na); na = fmaf(av[u].y, av[u].y, na);
                na = fmaf(av[u].z, av[u].z, na); na = fmaf(av[u].w, av[u].w, na);
            }
        }
        #pragma unroll
        for (int u = 0; u < 9; ++u) {
            nt = fmaf(t[nxt][u].x, t[nxt][u].x, nt); nt = fmaf(t[nxt][u].y, t[nxt][u].y, nt);
            nt = fmaf(t[nxt][u].z, t[nxt][u].z, nt); nt = fmaf(t[nxt][u].w, t[nxt][u].w, nt);
        }

        #pragma unroll
        for (int off = 16; off; off >>= 1) {
            dr += __shfl_xor_sync(~0u, dr, off);
            dd += __shfl_xor_sync(~0u, dd, off);
            na += __shfl_xor_sync(~0u, na, off);
            nt += __shfl_xor_sync(~0u, nt, off);
        }
        ntt[nxt] = nt;

        if (lane == 0) {
            const float nA = fmaxf(sqrtf(na), EPS);
            float rr = -1.f, dn = -1.f;
            if (vr) rr = dr / (nA * fmaxf(sqrtf(ntt[cur]), EPS));
            if (vd) dn = dd / (nA * fmaxf(sqrtf(ntt[nxt]), EPS));
            out[f * TPF + colm]         = rr;
            out[TOTAL + f * TPF + colm] = dn;
        }
    }
}

extern "C" void kernel_launch(void* const* d_in, const int* in_sizes, int n_in,
                              void* d_out, int out_size) {
    const float* x = (const float*)d_in[0];
    float* out = (float*)d_out;

    chain_kernel<<<GRID_BLOCKS, 256>>>(x, out);
}